// round 3
// baseline (speedup 1.0000x reference)
#include <cuda_runtime.h>
#include <math.h>
#include <stdint.h>

#define FDIM 64
#define HIDD 128
#define MSG  64
#define OUTF 64
#define GIN  (FDIM + HIDD)   // 192
#define G3   (3 * OUTF)      // 192
#define NMAX 50000

// scratch (no cudaMalloc allowed)
__device__ float g_y[NMAX * MSG];          // mailbox max, 12.8 MB
__device__ float g_Wih_t[GIN * G3];        // transposed: [i][o], o contiguous
__device__ float g_Whh_t[OUTF * G3];       // transposed: [j][o]

// ---------------------------------------------------------------------------
// init: zero mailbox + transpose GRU weights
// ---------------------------------------------------------------------------
__global__ void init_kernel(const float* __restrict__ W_ih,
                            const float* __restrict__ W_hh, int N)
{
    int idx = blockIdx.x * blockDim.x + threadIdx.x;
    if (idx < N * MSG) g_y[idx] = 0.0f;
    if (idx < G3 * GIN) {            // W_ih [o][i] -> Wt [i][o]
        int o = idx / GIN, i = idx % GIN;
        g_Wih_t[i * G3 + o] = W_ih[idx];
    }
    if (idx < G3 * OUTF) {           // W_hh [o][j] -> Wt [j][o]
        int o = idx / OUTF, j = idx % OUTF;
        g_Whh_t[j * G3 + o] = W_hh[idx];
    }
}

// ---------------------------------------------------------------------------
// edge kernel: gather x[src] -> MLP(64->128->64) -> gumbel softmax -> atomicMax
// 4 edges per warp, weights in shared memory
// ---------------------------------------------------------------------------
__global__ void __launch_bounds__(256, 3)
edge_kernel(const float* __restrict__ x,
            const int*   __restrict__ src,
            const int*   __restrict__ dst,
            const float* __restrict__ u,
            const float* __restrict__ W1,
            const float* __restrict__ b1,
            const float* __restrict__ W2,
            const float* __restrict__ b2,
            int E)
{
    extern __shared__ float sm[];
    float* sW1 = sm;                    // 64*128
    float* sW2 = sW1 + 64 * 128;        // 128*64  ([i][o], o contiguous)
    float* sb1 = sW2 + 128 * 64;        // 128
    float* sb2 = sb1 + 128;             // 64
    float* sxs = sb2 + 64;              // 8 warps * 4 edges * 64

    const int tid = threadIdx.x;
    for (int t = tid; t < 64 * 128; t += blockDim.x) sW1[t] = W1[t];
    for (int t = tid; t < 128 * 64; t += blockDim.x) sW2[t] = W2[t];
    if (tid < 128) sb1[tid] = b1[tid];
    if (tid < 64)  sb2[tid] = b2[tid];
    __syncthreads();

    const int warp = tid >> 5, lane = tid & 31;
    float* xs = sxs + warp * (4 * 64);
    const int nwarps = gridDim.x * (blockDim.x >> 5);
    const int gw = blockIdx.x * (blockDim.x >> 5) + warp;
    const unsigned FULL = 0xffffffffu;

    for (int base = gw * 4; base < E; base += nwarps * 4) {
        int sreg = 0, dreg = 0;
        if (lane < 4 && base + lane < E) {
            sreg = src[base + lane];
            dreg = dst[base + lane];
        }
        #pragma unroll
        for (int e = 0; e < 4; e++) {
            int se = __shfl_sync(FULL, sreg, e);
            const float* xp = x + (size_t)se * FDIM;
            xs[e * 64 + lane]      = xp[lane];
            xs[e * 64 + 32 + lane] = xp[32 + lane];
        }
        __syncwarp();

        // ---- layer 1: hid[o] = relu(b1[o] + sum_i x[i]*W1[i][o]), o = lane*4+q
        float acc[4][4];
        {
            float4 bv = *(const float4*)(sb1 + lane * 4);
            #pragma unroll
            for (int e = 0; e < 4; e++) {
                acc[e][0] = bv.x; acc[e][1] = bv.y; acc[e][2] = bv.z; acc[e][3] = bv.w;
            }
        }
        #pragma unroll 8
        for (int i = 0; i < 64; i++) {
            float4 w = *(const float4*)(sW1 + i * 128 + lane * 4);
            #pragma unroll
            for (int e = 0; e < 4; e++) {
                float xi = xs[e * 64 + i];
                acc[e][0] += xi * w.x; acc[e][1] += xi * w.y;
                acc[e][2] += xi * w.z; acc[e][3] += xi * w.w;
            }
        }
        #pragma unroll
        for (int e = 0; e < 4; e++) {
            acc[e][0] = fmaxf(acc[e][0], 0.f); acc[e][1] = fmaxf(acc[e][1], 0.f);
            acc[e][2] = fmaxf(acc[e][2], 0.f); acc[e][3] = fmaxf(acc[e][3], 0.f);
        }

        // ---- layer 2: logit[o] = b2[o] + sum_i hid[i]*W2[i][o], o = lane*2+r
        float lg[4][2];
        #pragma unroll
        for (int e = 0; e < 4; e++) {
            lg[e][0] = sb2[lane * 2];
            lg[e][1] = sb2[lane * 2 + 1];
        }
        #pragma unroll 2
        for (int i32 = 0; i32 < 32; i32++) {
            #pragma unroll
            for (int q = 0; q < 4; q++) {
                float2 w2 = *(const float2*)(sW2 + (i32 * 4 + q) * 64 + lane * 2);
                #pragma unroll
                for (int e = 0; e < 4; e++) {
                    float hv = __shfl_sync(FULL, acc[e][q], i32);
                    lg[e][0] += hv * w2.x;
                    lg[e][1] += hv * w2.y;
                }
            }
        }

        // ---- gumbel softmax (tau=0.1) + atomicMax scatter into mailbox
        #pragma unroll
        for (int e = 0; e < 4; e++) {
            if (base + e >= E) break;   // warp-uniform
            size_t eb = (size_t)(base + e) * MSG;
            float2 uv = *(const float2*)(u + eb + lane * 2);
            // precise logf: double-log is ill-conditioned near u->1
            float g0 = -logf(-logf(uv.x + 1e-10f) + 1e-10f);
            float g1 = -logf(-logf(uv.y + 1e-10f) + 1e-10f);
            float a0 = (lg[e][0] + g0) * 10.0f;
            float a1 = (lg[e][1] + g1) * 10.0f;
            float mx = fmaxf(a0, a1);
            #pragma unroll
            for (int o = 16; o > 0; o >>= 1) mx = fmaxf(mx, __shfl_xor_sync(FULL, mx, o));
            float e0 = __expf(a0 - mx), e1 = __expf(a1 - mx);
            float s = e0 + e1;
            #pragma unroll
            for (int o = 16; o > 0; o >>= 1) s += __shfl_xor_sync(FULL, s, o);
            float inv = __fdividef(1.0f, s);
            int de = __shfl_sync(FULL, dreg, e);
            int* yp = (int*)(g_y + (size_t)de * MSG);
            // softmax outputs strictly positive -> int compare == float compare
            atomicMax(yp + lane * 2,     __float_as_int(e0 * inv));
            atomicMax(yp + lane * 2 + 1, __float_as_int(e1 * inv));
        }
    }
}

// ---------------------------------------------------------------------------
// node kernel: dec = relu(y@Wdec+b), GRU(concat(x,dec), z)
// 4 nodes per warp, GRU weights (transposed) via L1-cached LDG
// ---------------------------------------------------------------------------
__device__ __forceinline__ float sigmoidf(float v) {
    return __fdividef(1.0f, 1.0f + __expf(-v));
}

__global__ void __launch_bounds__(256, 2)
node_kernel(const float* __restrict__ x,
            const float* __restrict__ z,
            const float* __restrict__ Wdec,
            const float* __restrict__ bdec,
            const float* __restrict__ bih,
            const float* __restrict__ bhh,
            float* __restrict__ out,
            int N, int HALF, int two)
{
    __shared__ float inps[8][4][GIN];   // [warp][node][x(64) | dec(128)]
    __shared__ float ys[8][4][64];      // y, then reused for z

    const int tid = threadIdx.x, warp = tid >> 5, lane = tid & 31;
    const int nb = (blockIdx.x * 8 + warp) * 4;
    if (nb >= N) return;

    #pragma unroll
    for (int e = 0; e < 4; e++) {
        int n = min(nb + e, N - 1);
        const float* xp = x + (size_t)n * 64;
        inps[warp][e][lane]      = xp[lane];
        inps[warp][e][32 + lane] = xp[32 + lane];
        const float* yp = g_y + (size_t)n * 64;
        ys[warp][e][lane]      = yp[lane];
        ys[warp][e][32 + lane] = yp[32 + lane];
    }
    __syncwarp();

    // ---- dec[h] = relu(bdec[h] + sum_j y[j]*Wdec[j][h]), h = lane*4+q
    float dacc[4][4];
    {
        float4 bd = *(const float4*)(bdec + lane * 4);
        #pragma unroll
        for (int e = 0; e < 4; e++) {
            dacc[e][0] = bd.x; dacc[e][1] = bd.y; dacc[e][2] = bd.z; dacc[e][3] = bd.w;
        }
    }
    #pragma unroll 8
    for (int j = 0; j < 64; j++) {
        float4 w = *(const float4*)(Wdec + j * 128 + lane * 4);
        #pragma unroll
        for (int e = 0; e < 4; e++) {
            float yv = ys[warp][e][j];
            dacc[e][0] += yv * w.x; dacc[e][1] += yv * w.y;
            dacc[e][2] += yv * w.z; dacc[e][3] += yv * w.w;
        }
    }
    #pragma unroll
    for (int e = 0; e < 4; e++) {
        float4 dv = make_float4(fmaxf(dacc[e][0], 0.f), fmaxf(dacc[e][1], 0.f),
                                fmaxf(dacc[e][2], 0.f), fmaxf(dacc[e][3], 0.f));
        *(float4*)&inps[warp][e][64 + lane * 4] = dv;
    }
    __syncwarp();

    // reuse ys for z
    #pragma unroll
    for (int e = 0; e < 4; e++) {
        int n = min(nb + e, N - 1);
        const float* zp = z + (size_t)n * 64;
        ys[warp][e][lane]      = zp[lane];
        ys[warp][e][32 + lane] = zp[32 + lane];
    }
    __syncwarp();

    // ---- gi[o] = bih[o] + sum_i inp[i]*Wih[o][i], o = k*64 + lane*2 + r
    float gia[4][6];
    #pragma unroll
    for (int k = 0; k < 3; k++) {
        float2 bv = *(const float2*)(bih + k * 64 + lane * 2);
        #pragma unroll
        for (int e = 0; e < 4; e++) { gia[e][2 * k] = bv.x; gia[e][2 * k + 1] = bv.y; }
    }
    #pragma unroll 4
    for (int i = 0; i < GIN; i++) {
        const float* wt = g_Wih_t + i * G3;
        float2 w0 = *(const float2*)(wt + lane * 2);
        float2 w1 = *(const float2*)(wt + 64 + lane * 2);
        float2 w2v = *(const float2*)(wt + 128 + lane * 2);
        #pragma unroll
        for (int e = 0; e < 4; e++) {
            float v = inps[warp][e][i];
            gia[e][0] += v * w0.x;  gia[e][1] += v * w0.y;
            gia[e][2] += v * w1.x;  gia[e][3] += v * w1.y;
            gia[e][4] += v * w2v.x; gia[e][5] += v * w2v.y;
        }
    }

    // ---- gh[o] = bhh[o] + sum_j z[j]*Whh[o][j]
    float gha[4][6];
    #pragma unroll
    for (int k = 0; k < 3; k++) {
        float2 bv = *(const float2*)(bhh + k * 64 + lane * 2);
        #pragma unroll
        for (int e = 0; e < 4; e++) { gha[e][2 * k] = bv.x; gha[e][2 * k + 1] = bv.y; }
    }
    #pragma unroll 4
    for (int j = 0; j < 64; j++) {
        const float* wt = g_Whh_t + j * G3;
        float2 w0 = *(const float2*)(wt + lane * 2);
        float2 w1 = *(const float2*)(wt + 64 + lane * 2);
        float2 w2v = *(const float2*)(wt + 128 + lane * 2);
        #pragma unroll
        for (int e = 0; e < 4; e++) {
            float v = ys[warp][e][j];
            gha[e][0] += v * w0.x;  gha[e][1] += v * w0.y;
            gha[e][2] += v * w1.x;  gha[e][3] += v * w1.y;
            gha[e][4] += v * w2v.x; gha[e][5] += v * w2v.y;
        }
    }

    // ---- gates + output (gate order r, z, n)
    #pragma unroll
    for (int e = 0; e < 4; e++) {
        int n = nb + e;
        if (n >= N) break;
        float zc0 = ys[warp][e][lane * 2];
        float zc1 = ys[warp][e][lane * 2 + 1];
        float r0 = sigmoidf(gia[e][0] + gha[e][0]);
        float r1 = sigmoidf(gia[e][1] + gha[e][1]);
        float zg0 = sigmoidf(gia[e][2] + gha[e][2]);
        float zg1 = sigmoidf(gia[e][3] + gha[e][3]);
        float n0 = tanhf(gia[e][4] + r0 * gha[e][4]);
        float n1 = tanhf(gia[e][5] + r1 * gha[e][5]);
        float h0 = (1.0f - zg0) * n0 + zg0 * zc0;
        float h1 = (1.0f - zg1) * n1 + zg1 * zc1;
        size_t off = (size_t)n * 64 + lane * 2;
        out[off] = h0; out[off + 1] = h1;
        if (two) { out[HALF + off] = h0; out[HALF + off + 1] = h1; }
    }
}

// ---------------------------------------------------------------------------
// launch
// inputs: x, z, src, dst, u, W_enc1, b_enc1, W_enc2, b_enc2,
//         W_dec, b_dec, W_ih, b_ih, W_hh, b_hh
// ---------------------------------------------------------------------------
extern "C" void kernel_launch(void* const* d_in, const int* in_sizes, int n_in,
                              void* d_out, int out_size)
{
    const float* x     = (const float*)d_in[0];
    const float* z     = (const float*)d_in[1];
    const int*   src   = (const int*)  d_in[2];
    const int*   dst   = (const int*)  d_in[3];
    const float* u     = (const float*)d_in[4];
    const float* W1    = (const float*)d_in[5];
    const float* b1    = (const float*)d_in[6];
    const float* W2    = (const float*)d_in[7];
    const float* b2    = (const float*)d_in[8];
    const float* Wdec  = (const float*)d_in[9];
    const float* bdec  = (const float*)d_in[10];
    const float* Wih   = (const float*)d_in[11];
    const float* bih   = (const float*)d_in[12];
    const float* Whh   = (const float*)d_in[13];
    const float* bhh   = (const float*)d_in[14];

    const int N = in_sizes[0] / FDIM;
    const int E = in_sizes[2];
    float* out = (float*)d_out;
    const int HALF = N * OUTF;
    const int two = (out_size >= 2 * HALF) ? 1 : 0;

    // init mailbox + transposes
    {
        int total = N * MSG;
        init_kernel<<<(total + 255) / 256, 256>>>(Wih, Whh, N);
    }

    // edge kernel: dynamic smem (64KB weights + x staging)
    {
        const int smem = (64 * 128 + 128 * 64 + 128 + 64 + 8 * 4 * 64) * (int)sizeof(float);
        static int attr_set = 0;
        cudaFuncSetAttribute(edge_kernel, cudaFuncAttributeMaxDynamicSharedMemorySize, smem);
        (void)attr_set;
        int blocks = 456;  // ~3 per SM, warp-stride loop covers all edges
        edge_kernel<<<blocks, 256, smem>>>(x, src, dst, u, W1, b1, W2, b2, E);
    }

    // node kernel
    {
        int blocks = (N + 31) / 32;  // 8 warps * 4 nodes per block
        node_kernel<<<blocks, 256>>>(x, z, Wdec, bdec, bih, bhh, out, N, HALF, two);
    }
}

// round 5
// speedup vs baseline: 2.0900x; 2.0900x over previous
#include <cuda_runtime.h>
#include <math.h>
#include <stdint.h>

#define FDIM 64
#define HIDD 128
#define MSG  64
#define OUTF 64
#define GIN  (FDIM + HIDD)   // 192
#define G3   (3 * OUTF)      // 192
#define NMAX 50000

// scratch (no cudaMalloc allowed)
__device__ float g_y[NMAX * MSG];          // mailbox max, 12.8 MB
__device__ float g_Wih_t[GIN * G3];        // transposed: [i][o]
__device__ float g_Whh_t[OUTF * G3];       // transposed: [j][o]

// ===========================================================================
// helpers
// ===========================================================================
__device__ __forceinline__ uint32_t cvt_tf32(float f) {
    uint32_t r; asm("cvt.rna.tf32.f32 %0, %1;" : "=r"(r) : "f"(f)); return r;
}
__device__ __forceinline__ float tf32f(float f) {
    return __uint_as_float(cvt_tf32(f));
}
// D += A(16x8) * B(8x8), tf32 inputs, f32 accum  (arch-portable: sm_80+)
__device__ __forceinline__ void mma8(float* c, uint32_t a0, uint32_t a1,
                                     uint32_t a2, uint32_t a3,
                                     uint32_t b0, uint32_t b1) {
    asm volatile(
        "mma.sync.aligned.m16n8k8.row.col.f32.tf32.tf32.f32 "
        "{%0,%1,%2,%3}, {%4,%5,%6,%7}, {%8,%9}, {%0,%1,%2,%3};"
        : "+f"(c[0]), "+f"(c[1]), "+f"(c[2]), "+f"(c[3])
        : "r"(a0), "r"(a1), "r"(a2), "r"(a3), "r"(b0), "r"(b1));
}

// smem layout (bytes, dynamic)
#define OFF_W1F   0                    // 16 nslab x 8 kslab x 32 lane x float2 = 32KB
#define OFF_W2F   32768                // 8 nslab x 16 kslab x 32 lane x float2 = 32KB
#define OFF_SB1   65536                // 128 f
#define OFF_SB2   66048                // 64 f
#define OFF_STRIP 66304                // 16 warps x 2112 floats (16 rows x 132)
#define STRIP_F   2112
#define SMEM_EDGE (OFF_STRIP + 16 * STRIP_F * 4)   // 201472

// ---------------------------------------------------------------------------
// init: zero mailbox + transpose GRU weights
// ---------------------------------------------------------------------------
__global__ void init_kernel(const float* __restrict__ W_ih,
                            const float* __restrict__ W_hh, int N)
{
    int idx = blockIdx.x * blockDim.x + threadIdx.x;
    if (idx < N * MSG) g_y[idx] = 0.0f;
    if (idx < G3 * GIN) {
        int o = idx / GIN, i = idx % GIN;
        g_Wih_t[i * G3 + o] = W_ih[idx];
    }
    if (idx < G3 * OUTF) {
        int o = idx / OUTF, j = idx % OUTF;
        g_Whh_t[j * G3 + o] = W_hh[idx];
    }
}

// ---------------------------------------------------------------------------
// edge kernel (mma.sync tf32): persistent, tile = 256 edges, warp = 16 edges
//   GEMM1: H[16,128] = X[16,64] @ W1, relu+bias, in-strip (pass order 8..15, 0..7)
//   GEMM2: L[16,64]  = H[16,128] @ W2
//   epi:   gumbel softmax (tau=0.1) + thresholded atomicMax scatter into g_y
// ---------------------------------------------------------------------------
__global__ void __launch_bounds__(512, 1)
edge_mma_kernel(const float* __restrict__ x, const int* __restrict__ src,
                const int* __restrict__ dst, const float* __restrict__ u,
                const float* __restrict__ W1, const float* __restrict__ b1,
                const float* __restrict__ W2, const float* __restrict__ b2,
                int E)
{
    extern __shared__ unsigned char smraw[];
    float2* w1f = (float2*)(smraw + OFF_W1F);
    float2* w2f = (float2*)(smraw + OFF_W2F);
    float*  sb1 = (float*)(smraw + OFF_SB1);
    float*  sb2 = (float*)(smraw + OFF_SB2);

    const int tid = threadIdx.x;
    const int warp = tid >> 5, lane = tid & 31;
    const int t = lane & 3, g = lane >> 2;
    const unsigned FULL = 0xffffffffu;
    float* strip = (float*)(smraw + OFF_STRIP) + warp * STRIP_F;

    // ---- pack weights into mma fragment order (tf32-rounded), once
    for (int idx = tid; idx < 16 * 8 * 32; idx += 512) {
        int ln = idx & 31, ks = (idx >> 5) & 7, ns = idx >> 8;
        int tt = ln & 3, gg = ln >> 2;
        w1f[idx] = make_float2(tf32f(W1[(ks * 8 + tt) * 128 + ns * 8 + gg]),
                               tf32f(W1[(ks * 8 + tt + 4) * 128 + ns * 8 + gg]));
    }
    for (int idx = tid; idx < 8 * 16 * 32; idx += 512) {
        int ln = idx & 31, ks = (idx >> 5) & 15, ns = idx >> 9;
        int tt = ln & 3, gg = ln >> 2;
        w2f[idx] = make_float2(tf32f(W2[(ks * 8 + tt) * 64 + ns * 8 + gg]),
                               tf32f(W2[(ks * 8 + tt + 4) * 64 + ns * 8 + gg]));
    }
    if (tid < 128) sb1[tid] = b1[tid];
    if (tid < 64)  sb2[tid] = b2[tid];
    __syncthreads();

    const int ntiles = (E + 255) >> 8;
    const int r0 = warp * 16;

    for (int tile = blockIdx.x; tile < ntiles; tile += gridDim.x) {
        const int base = tile << 8;
        __syncwarp();   // strip reuse across tiles

        // ---- gather X[src] -> strip cols 0..63 (stride 132), tf32
        {
            int r = lane >> 1;                 // 0..15
            int ch = (lane & 1) * 32;          // col half
            int e = base + r0 + r;
            int s = src[min(e, E - 1)];
            const float4* xp = (const float4*)(x + (size_t)s * 64 + ch);
            float* dp = strip + r * 132 + ch;
            #pragma unroll
            for (int i = 0; i < 8; i++) {
                float4 v = xp[i];
                dp[i * 4 + 0] = tf32f(v.x); dp[i * 4 + 1] = tf32f(v.y);
                dp[i * 4 + 2] = tf32f(v.z); dp[i * 4 + 3] = tf32f(v.w);
            }
        }
        __syncwarp();

        // ---- GEMM1 in two passes: n-slabs {8..15} then {0..7}
        #pragma unroll
        for (int pass = 0; pass < 2; pass++) {
            const int nbase = pass ? 0 : 8;
            float acc[8][4];
            #pragma unroll
            for (int ns = 0; ns < 8; ns++)
                { acc[ns][0] = acc[ns][1] = acc[ns][2] = acc[ns][3] = 0.f; }

            for (int ks = 0; ks < 8; ks++) {
                uint32_t a0 = __float_as_uint(strip[g * 132 + ks * 8 + t]);
                uint32_t a1 = __float_as_uint(strip[(g + 8) * 132 + ks * 8 + t]);
                uint32_t a2 = __float_as_uint(strip[g * 132 + ks * 8 + t + 4]);
                uint32_t a3 = __float_as_uint(strip[(g + 8) * 132 + ks * 8 + t + 4]);
                #pragma unroll
                for (int ns = 0; ns < 8; ns++) {
                    float2 b = w1f[((nbase + ns) * 8 + ks) * 32 + lane];
                    mma8(acc[ns], a0, a1, a2, a3,
                         __float_as_uint(b.x), __float_as_uint(b.y));
                }
            }
            // epi1: relu(+b1) -> H cols (nbase+ns)*8+2t (pass0 cols 64..127)
            #pragma unroll
            for (int ns = 0; ns < 8; ns++) {
                int c = (nbase + ns) * 8 + 2 * t;
                float bx = sb1[c], by = sb1[c + 1];
                strip[g * 132 + c]           = tf32f(fmaxf(acc[ns][0] + bx, 0.f));
                strip[g * 132 + c + 1]       = tf32f(fmaxf(acc[ns][1] + by, 0.f));
                strip[(g + 8) * 132 + c]     = tf32f(fmaxf(acc[ns][2] + bx, 0.f));
                strip[(g + 8) * 132 + c + 1] = tf32f(fmaxf(acc[ns][3] + by, 0.f));
            }
        }
        __syncwarp();

        // ---- GEMM2: L[16,64] = H[16,128] @ W2
        float acc2[8][4];
        #pragma unroll
        for (int ns = 0; ns < 8; ns++)
            { acc2[ns][0] = acc2[ns][1] = acc2[ns][2] = acc2[ns][3] = 0.f; }
        for (int ks = 0; ks < 16; ks++) {
            uint32_t a0 = __float_as_uint(strip[g * 132 + ks * 8 + t]);
            uint32_t a1 = __float_as_uint(strip[(g + 8) * 132 + ks * 8 + t]);
            uint32_t a2 = __float_as_uint(strip[g * 132 + ks * 8 + t + 4]);
            uint32_t a3 = __float_as_uint(strip[(g + 8) * 132 + ks * 8 + t + 4]);
            #pragma unroll
            for (int ns = 0; ns < 8; ns++) {
                float2 b = w2f[(ns * 16 + ks) * 32 + lane];
                mma8(acc2[ns], a0, a1, a2, a3,
                     __float_as_uint(b.x), __float_as_uint(b.y));
            }
        }

        // ---- epi2: gumbel softmax + scatter. Thread owns 16 cols of rows
        //      (r0+g) and (r0+g+8); quad {4g..4g+3} covers a full row.
        {
            const int e_lo = base + r0 + g, e_hi = e_lo + 8;
            const bool vlo = e_lo < E, vhi = e_hi < E;
            float alo[16], ahi[16];
            float mlo = -1e30f, mhi = -1e30f;
            #pragma unroll
            for (int ns = 0; ns < 8; ns++) {
                int c = ns * 8 + 2 * t;
                float b2x = sb2[c], b2y = sb2[c + 1];
                float2 ul = vlo ? *(const float2*)(u + (size_t)e_lo * 64 + c)
                               : make_float2(0.5f, 0.5f);
                float2 uh = vhi ? *(const float2*)(u + (size_t)e_hi * 64 + c)
                               : make_float2(0.5f, 0.5f);
                // precise logf: double-log ill-conditioned near u->1
                float gl0 = -logf(-logf(ul.x + 1e-10f) + 1e-10f);
                float gl1 = -logf(-logf(ul.y + 1e-10f) + 1e-10f);
                float gh0 = -logf(-logf(uh.x + 1e-10f) + 1e-10f);
                float gh1 = -logf(-logf(uh.y + 1e-10f) + 1e-10f);
                alo[2*ns]   = (acc2[ns][0] + b2x + gl0) * 10.0f;
                alo[2*ns+1] = (acc2[ns][1] + b2y + gl1) * 10.0f;
                ahi[2*ns]   = (acc2[ns][2] + b2x + gh0) * 10.0f;
                ahi[2*ns+1] = (acc2[ns][3] + b2y + gh1) * 10.0f;
                mlo = fmaxf(mlo, fmaxf(alo[2*ns], alo[2*ns+1]));
                mhi = fmaxf(mhi, fmaxf(ahi[2*ns], ahi[2*ns+1]));
            }
            mlo = fmaxf(mlo, __shfl_xor_sync(FULL, mlo, 1));
            mlo = fmaxf(mlo, __shfl_xor_sync(FULL, mlo, 2));
            mhi = fmaxf(mhi, __shfl_xor_sync(FULL, mhi, 1));
            mhi = fmaxf(mhi, __shfl_xor_sync(FULL, mhi, 2));
            float slo = 0.f, shi = 0.f;
            #pragma unroll
            for (int i = 0; i < 16; i++) {
                alo[i] = __expf(alo[i] - mlo); slo += alo[i];
                ahi[i] = __expf(ahi[i] - mhi); shi += ahi[i];
            }
            slo += __shfl_xor_sync(FULL, slo, 1);
            slo += __shfl_xor_sync(FULL, slo, 2);
            shi += __shfl_xor_sync(FULL, shi, 1);
            shi += __shfl_xor_sync(FULL, shi, 2);
            float ilo = __fdividef(1.0f, slo), ihi = __fdividef(1.0f, shi);
            // softmax strictly positive -> int compare == float compare.
            // skip values < 1e-7: y abs error <= 1e-7, invisible at 1e-3 rel_err
            if (vlo) {
                int* yp = (int*)(g_y + (size_t)dst[e_lo] * 64);
                #pragma unroll
                for (int ns = 0; ns < 8; ns++) {
                    float v0 = alo[2*ns] * ilo, v1 = alo[2*ns+1] * ilo;
                    if (v0 > 1e-7f) atomicMax(yp + ns*8 + 2*t,     __float_as_int(v0));
                    if (v1 > 1e-7f) atomicMax(yp + ns*8 + 2*t + 1, __float_as_int(v1));
                }
            }
            if (vhi) {
                int* yp = (int*)(g_y + (size_t)dst[e_hi] * 64);
                #pragma unroll
                for (int ns = 0; ns < 8; ns++) {
                    float v0 = ahi[2*ns] * ihi, v1 = ahi[2*ns+1] * ihi;
                    if (v0 > 1e-7f) atomicMax(yp + ns*8 + 2*t,     __float_as_int(v0));
                    if (v1 > 1e-7f) atomicMax(yp + ns*8 + 2*t + 1, __float_as_int(v1));
                }
            }
        }
    }
}

// ---------------------------------------------------------------------------
// node kernel: dec = relu(y@Wdec+b), GRU(concat(x,dec), z)  (unchanged, passing)
// ---------------------------------------------------------------------------
__device__ __forceinline__ float sigmoidf(float v) {
    return __fdividef(1.0f, 1.0f + __expf(-v));
}

__global__ void __launch_bounds__(256, 2)
node_kernel(const float* __restrict__ x,
            const float* __restrict__ z,
            const float* __restrict__ Wdec,
            const float* __restrict__ bdec,
            const float* __restrict__ bih,
            const float* __restrict__ bhh,
            float* __restrict__ out,
            int N, int HALF, int two)
{
    __shared__ float inps[8][4][GIN];
    __shared__ float ys[8][4][64];

    const int tid = threadIdx.x, warp = tid >> 5, lane = tid & 31;
    const int nb = (blockIdx.x * 8 + warp) * 4;
    if (nb >= N) return;

    #pragma unroll
    for (int e = 0; e < 4; e++) {
        int n = min(nb + e, N - 1);
        const float* xp = x + (size_t)n * 64;
        inps[warp][e][lane]      = xp[lane];
        inps[warp][e][32 + lane] = xp[32 + lane];
        const float* yp = g_y + (size_t)n * 64;
        ys[warp][e][lane]      = yp[lane];
        ys[warp][e][32 + lane] = yp[32 + lane];
    }
    __syncwarp();

    float dacc[4][4];
    {
        float4 bd = *(const float4*)(bdec + lane * 4);
        #pragma unroll
        for (int e = 0; e < 4; e++) {
            dacc[e][0] = bd.x; dacc[e][1] = bd.y; dacc[e][2] = bd.z; dacc[e][3] = bd.w;
        }
    }
    #pragma unroll 8
    for (int j = 0; j < 64; j++) {
        float4 w = *(const float4*)(Wdec + j * 128 + lane * 4);
        #pragma unroll
        for (int e = 0; e < 4; e++) {
            float yv = ys[warp][e][j];
            dacc[e][0] += yv * w.x; dacc[e][1] += yv * w.y;
            dacc[e][2] += yv * w.z; dacc[e][3] += yv * w.w;
        }
    }
    #pragma unroll
    for (int e = 0; e < 4; e++) {
        float4 dv = make_float4(fmaxf(dacc[e][0], 0.f), fmaxf(dacc[e][1], 0.f),
                                fmaxf(dacc[e][2], 0.f), fmaxf(dacc[e][3], 0.f));
        *(float4*)&inps[warp][e][64 + lane * 4] = dv;
    }
    __syncwarp();

    #pragma unroll
    for (int e = 0; e < 4; e++) {
        int n = min(nb + e, N - 1);
        const float* zp = z + (size_t)n * 64;
        ys[warp][e][lane]      = zp[lane];
        ys[warp][e][32 + lane] = zp[32 + lane];
    }
    __syncwarp();

    float gia[4][6];
    #pragma unroll
    for (int k = 0; k < 3; k++) {
        float2 bv = *(const float2*)(bih + k * 64 + lane * 2);
        #pragma unroll
        for (int e = 0; e < 4; e++) { gia[e][2 * k] = bv.x; gia[e][2 * k + 1] = bv.y; }
    }
    #pragma unroll 4
    for (int i = 0; i < GIN; i++) {
        const float* wt = g_Wih_t + i * G3;
        float2 w0 = *(const float2*)(wt + lane * 2);
        float2 w1 = *(const float2*)(wt + 64 + lane * 2);
        float2 w2v = *(const float2*)(wt + 128 + lane * 2);
        #pragma unroll
        for (int e = 0; e < 4; e++) {
            float v = inps[warp][e][i];
            gia[e][0] += v * w0.x;  gia[e][1] += v * w0.y;
            gia[e][2] += v * w1.x;  gia[e][3] += v * w1.y;
            gia[e][4] += v * w2v.x; gia[e][5] += v * w2v.y;
        }
    }

    float gha[4][6];
    #pragma unroll
    for (int k = 0; k < 3; k++) {
        float2 bv = *(const float2*)(bhh + k * 64 + lane * 2);
        #pragma unroll
        for (int e = 0; e < 4; e++) { gha[e][2 * k] = bv.x; gha[e][2 * k + 1] = bv.y; }
    }
    #pragma unroll 4
    for (int j = 0; j < 64; j++) {
        const float* wt = g_Whh_t + j * G3;
        float2 w0 = *(const float2*)(wt + lane * 2);
        float2 w1 = *(const float2*)(wt + 64 + lane * 2);
        float2 w2v = *(const float2*)(wt + 128 + lane * 2);
        #pragma unroll
        for (int e = 0; e < 4; e++) {
            float v = ys[warp][e][j];
            gha[e][0] += v * w0.x;  gha[e][1] += v * w0.y;
            gha[e][2] += v * w1.x;  gha[e][3] += v * w1.y;
            gha[e][4] += v * w2v.x; gha[e][5] += v * w2v.y;
        }
    }

    #pragma unroll
    for (int e = 0; e < 4; e++) {
        int n = nb + e;
        if (n >= N) break;
        float zc0 = ys[warp][e][lane * 2];
        float zc1 = ys[warp][e][lane * 2 + 1];
        float r0 = sigmoidf(gia[e][0] + gha[e][0]);
        float r1 = sigmoidf(gia[e][1] + gha[e][1]);
        float zg0 = sigmoidf(gia[e][2] + gha[e][2]);
        float zg1 = sigmoidf(gia[e][3] + gha[e][3]);
        float n0 = tanhf(gia[e][4] + r0 * gha[e][4]);
        float n1 = tanhf(gia[e][5] + r1 * gha[e][5]);
        float h0 = (1.0f - zg0) * n0 + zg0 * zc0;
        float h1 = (1.0f - zg1) * n1 + zg1 * zc1;
        size_t off = (size_t)n * 64 + lane * 2;
        out[off] = h0; out[off + 1] = h1;
        if (two) { out[HALF + off] = h0; out[HALF + off + 1] = h1; }
    }
}

// ---------------------------------------------------------------------------
// launch
// inputs: x, z, src, dst, u, W_enc1, b_enc1, W_enc2, b_enc2,
//         W_dec, b_dec, W_ih, b_ih, W_hh, b_hh
// ---------------------------------------------------------------------------
extern "C" void kernel_launch(void* const* d_in, const int* in_sizes, int n_in,
                              void* d_out, int out_size)
{
    const float* x     = (const float*)d_in[0];
    const float* z     = (const float*)d_in[1];
    const int*   src   = (const int*)  d_in[2];
    const int*   dst   = (const int*)  d_in[3];
    const float* u     = (const float*)d_in[4];
    const float* W1    = (const float*)d_in[5];
    const float* b1    = (const float*)d_in[6];
    const float* W2    = (const float*)d_in[7];
    const float* b2    = (const float*)d_in[8];
    const float* Wdec  = (const float*)d_in[9];
    const float* bdec  = (const float*)d_in[10];
    const float* Wih   = (const float*)d_in[11];
    const float* bih   = (const float*)d_in[12];
    const float* Whh   = (const float*)d_in[13];
    const float* bhh   = (const float*)d_in[14];

    const int N = in_sizes[0] / FDIM;
    const int E = in_sizes[2];
    float* out = (float*)d_out;
    const int HALF = N * OUTF;
    const int two = (out_size >= 2 * HALF) ? 1 : 0;

    // init mailbox + transposes
    {
        int total = N * MSG;
        init_kernel<<<(total + 255) / 256, 256>>>(Wih, Whh, N);
    }

    // edge kernel: persistent mma.sync tf32
    {
        cudaFuncSetAttribute(edge_mma_kernel,
                             cudaFuncAttributeMaxDynamicSharedMemorySize, SMEM_EDGE);
        edge_mma_kernel<<<148, 512, SMEM_EDGE>>>(x, src, dst, u, W1, b1, W2, b2, E);
    }

    // node kernel
    {
        int blocks = (N + 31) / 32;
        node_kernel<<<blocks, 256>>>(x, z, Wdec, bdec, bih, bhh, out, N, HALF, two);
    }
}

// round 7
// speedup vs baseline: 3.0754x; 1.4715x over previous
#include <cuda_runtime.h>
#include <math.h>
#include <stdint.h>

#define FDIM 64
#define HIDD 128
#define MSG  64
#define OUTF 64
#define NMAX 50000

// scratch (no cudaMalloc allowed)
__device__ float g_y[NMAX * MSG];            // mailbox max, 12.8 MB
__device__ float2 g_WdecF[16 * 8 * 32];      // mma B-frags for Wdec
__device__ float2 g_WihF[24 * 24 * 32];      // mma B-frags for W_ih (gi)
__device__ float2 g_WhhF[24 * 8 * 32];       // mma B-frags for W_hh (gh)

// ===========================================================================
// helpers
// ===========================================================================
__device__ __forceinline__ uint32_t cvt_tf32(float f) {
    uint32_t r; asm("cvt.rna.tf32.f32 %0, %1;" : "=r"(r) : "f"(f)); return r;
}
__device__ __forceinline__ float tf32f(float f) {
    return __uint_as_float(cvt_tf32(f));
}
// D += A(16x8) * B(8x8), tf32 inputs, f32 accum  (arch-portable: sm_80+)
__device__ __forceinline__ void mma8(float* c, uint32_t a0, uint32_t a1,
                                     uint32_t a2, uint32_t a3,
                                     uint32_t b0, uint32_t b1) {
    asm volatile(
        "mma.sync.aligned.m16n8k8.row.col.f32.tf32.tf32.f32 "
        "{%0,%1,%2,%3}, {%4,%5,%6,%7}, {%8,%9}, {%0,%1,%2,%3};"
        : "+f"(c[0]), "+f"(c[1]), "+f"(c[2]), "+f"(c[3])
        : "r"(a0), "r"(a1), "r"(a2), "r"(a3), "r"(b0), "r"(b1));
}
__device__ __forceinline__ float sigmoidf(float v) {
    return __fdividef(1.0f, 1.0f + __expf(-v));
}

// edge kernel smem layout (bytes)
#define OFF_W1F   0                    // 16 ns x 8 ks x 32 lane x float2 = 32KB
#define OFF_W2F   32768                // 8 ns x 16 ks x 32 lane x float2 = 32KB
#define OFF_SB1   65536                // 128 f
#define OFF_SB2   66048                // 64 f  (pre-scaled 14.42695*b2)
#define OFF_STRIP 66304                // 16 warps x 2112 floats (16 rows x 132)
#define STRIP_F   2112
#define SMEM_EDGE (OFF_STRIP + 16 * STRIP_F * 4)   // 201472

// node kernel smem layout (floats)
#define NOD_STRIP 0                    // 8 warps x 16 x 196
#define NOD_YB    (8 * 3136)           // 8 warps x 16 x 68
#define NOD_ZB    (NOD_YB + 8 * 1088)
#define NOD_BR    (NOD_ZB + 8 * 1088)  // 128: bih+bhh (r,z gates)
#define NOD_BIN   (NOD_BR + 128)       // 64: bih n-gate
#define NOD_BHN   (NOD_BIN + 64)       // 64: bhh n-gate
#define NOD_BDEC  (NOD_BHN + 64)       // 128
#define SMEM_NODE ((NOD_BDEC + 128) * 4)

// ---------------------------------------------------------------------------
// init: zero mailbox + pack node-GEMM weight fragments
// ---------------------------------------------------------------------------
__global__ void init_kernel(const float* __restrict__ W_ih,
                            const float* __restrict__ W_hh,
                            const float* __restrict__ Wdec, int N)
{
    int idx = blockIdx.x * blockDim.x + threadIdx.x;
    if (idx < N * MSG) g_y[idx] = 0.0f;
    int lane = idx & 31, g = lane >> 2, t = lane & 3;
    if (idx < 16 * 8 * 32) {                 // WdecF: B[k=j][n=h] = Wdec[j*128+h]
        int ks = (idx >> 5) & 7, ns = idx >> 8;
        g_WdecF[idx] = make_float2(
            tf32f(Wdec[(ks * 8 + t) * 128 + ns * 8 + g]),
            tf32f(Wdec[(ks * 8 + t + 4) * 128 + ns * 8 + g]));
    }
    if (idx < 24 * 24 * 32) {                // WihF: B[k=i][n=o] = W_ih[o*192+i]
        int ks = (idx >> 5) % 24, ns = (idx >> 5) / 24;
        g_WihF[idx] = make_float2(
            tf32f(W_ih[(ns * 8 + g) * 192 + ks * 8 + t]),
            tf32f(W_ih[(ns * 8 + g) * 192 + ks * 8 + t + 4]));
    }
    if (idx < 24 * 8 * 32) {                 // WhhF: B[k=j][n=o] = W_hh[o*64+j]
        int ks = (idx >> 5) & 7, ns = idx >> 8;
        g_WhhF[idx] = make_float2(
            tf32f(W_hh[(ns * 8 + g) * 64 + ks * 8 + t]),
            tf32f(W_hh[(ns * 8 + g) * 64 + ks * 8 + t + 4]));
    }
}

// ---------------------------------------------------------------------------
// edge kernel (mma.sync tf32): persistent, tile = 256 edges, warp = 16 edges
//   GEMM1: H[16,128] = X[16,64] @ W1, relu+bias, in-strip
//   GEMM2: L[16,64]  = H[16,128] @ W2
//   epi:   gumbel softmax in log2 domain + thresholded atomicMax scatter
// ---------------------------------------------------------------------------
__global__ void __launch_bounds__(512, 1)
edge_mma_kernel(const float* __restrict__ x, const int* __restrict__ src,
                const int* __restrict__ dst, const float* __restrict__ u,
                const float* __restrict__ W1, const float* __restrict__ b1,
                const float* __restrict__ W2, const float* __restrict__ b2,
                int E)
{
    extern __shared__ unsigned char smraw[];
    float2* w1f = (float2*)(smraw + OFF_W1F);
    float2* w2f = (float2*)(smraw + OFF_W2F);
    float*  sb1 = (float*)(smraw + OFF_SB1);
    float*  sb2 = (float*)(smraw + OFF_SB2);

    const int tid = threadIdx.x;
    const int warp = tid >> 5, lane = tid & 31;
    const int t = lane & 3, g = lane >> 2;
    const unsigned FULL = 0xffffffffu;
    float* strip = (float*)(smraw + OFF_STRIP) + warp * STRIP_F;

    // ---- pack weights into mma fragment order (tf32-rounded), once
    for (int idx = tid; idx < 16 * 8 * 32; idx += 512) {
        int ln = idx & 31, ks = (idx >> 5) & 7, ns = idx >> 8;
        int tt = ln & 3, gg = ln >> 2;
        w1f[idx] = make_float2(tf32f(W1[(ks * 8 + tt) * 128 + ns * 8 + gg]),
                               tf32f(W1[(ks * 8 + tt + 4) * 128 + ns * 8 + gg]));
    }
    for (int idx = tid; idx < 8 * 16 * 32; idx += 512) {
        int ln = idx & 31, ks = (idx >> 5) & 15, ns = idx >> 9;
        int tt = ln & 3, gg = ln >> 2;
        w2f[idx] = make_float2(tf32f(W2[(ks * 8 + tt) * 64 + ns * 8 + gg]),
                               tf32f(W2[(ks * 8 + tt + 4) * 64 + ns * 8 + gg]));
    }
    if (tid < 128) sb1[tid] = b1[tid];
    if (tid < 64)  sb2[tid] = 14.42695041f * b2[tid];   // 10/tau * log2(e) folded
    __syncthreads();

    const int ntiles = (E + 255) >> 8;
    const int r0 = warp * 16;

    for (int tile = blockIdx.x; tile < ntiles; tile += gridDim.x) {
        const int base = tile << 8;
        __syncwarp();   // strip reuse across tiles

        // ---- gather X[src] -> strip cols 0..63 (stride 132), tf32
        {
            int r = lane >> 1;
            int ch = (lane & 1) * 32;
            int e = base + r0 + r;
            int s = src[min(e, E - 1)];
            const float4* xp = (const float4*)(x + (size_t)s * 64 + ch);
            float* dp = strip + r * 132 + ch;
            #pragma unroll
            for (int i = 0; i < 8; i++) {
                float4 v = xp[i];
                dp[i * 4 + 0] = tf32f(v.x); dp[i * 4 + 1] = tf32f(v.y);
                dp[i * 4 + 2] = tf32f(v.z); dp[i * 4 + 3] = tf32f(v.w);
            }
        }
        __syncwarp();

        // ---- GEMM1 in two passes: n-slabs {8..15} then {0..7}
        #pragma unroll
        for (int pass = 0; pass < 2; pass++) {
            const int nbase = pass ? 0 : 8;
            float acc[8][4];
            #pragma unroll
            for (int ns = 0; ns < 8; ns++)
                { acc[ns][0] = acc[ns][1] = acc[ns][2] = acc[ns][3] = 0.f; }

            for (int ks = 0; ks < 8; ks++) {
                uint32_t a0 = __float_as_uint(strip[g * 132 + ks * 8 + t]);
                uint32_t a1 = __float_as_uint(strip[(g + 8) * 132 + ks * 8 + t]);
                uint32_t a2 = __float_as_uint(strip[g * 132 + ks * 8 + t + 4]);
                uint32_t a3 = __float_as_uint(strip[(g + 8) * 132 + ks * 8 + t + 4]);
                #pragma unroll
                for (int ns = 0; ns < 8; ns++) {
                    float2 b = w1f[((nbase + ns) * 8 + ks) * 32 + lane];
                    mma8(acc[ns], a0, a1, a2, a3,
                         __float_as_uint(b.x), __float_as_uint(b.y));
                }
            }
            #pragma unroll
            for (int ns = 0; ns < 8; ns++) {
                int c = (nbase + ns) * 8 + 2 * t;
                float bx = sb1[c], by = sb1[c + 1];
                strip[g * 132 + c]           = tf32f(fmaxf(acc[ns][0] + bx, 0.f));
                strip[g * 132 + c + 1]       = tf32f(fmaxf(acc[ns][1] + by, 0.f));
                strip[(g + 8) * 132 + c]     = tf32f(fmaxf(acc[ns][2] + bx, 0.f));
                strip[(g + 8) * 132 + c + 1] = tf32f(fmaxf(acc[ns][3] + by, 0.f));
            }
        }
        __syncwarp();

        // ---- GEMM2: L[16,64] = H[16,128] @ W2
        float acc2[8][4];
        #pragma unroll
        for (int ns = 0; ns < 8; ns++)
            { acc2[ns][0] = acc2[ns][1] = acc2[ns][2] = acc2[ns][3] = 0.f; }
        for (int ks = 0; ks < 16; ks++) {
            uint32_t a0 = __float_as_uint(strip[g * 132 + ks * 8 + t]);
            uint32_t a1 = __float_as_uint(strip[(g + 8) * 132 + ks * 8 + t]);
            uint32_t a2 = __float_as_uint(strip[g * 132 + ks * 8 + t + 4]);
            uint32_t a3 = __float_as_uint(strip[(g + 8) * 132 + ks * 8 + t + 4]);
            #pragma unroll
            for (int ns = 0; ns < 8; ns++) {
                float2 b = w2f[(ns * 16 + ks) * 32 + lane];
                mma8(acc2[ns], a0, a1, a2, a3,
                     __float_as_uint(b.x), __float_as_uint(b.y));
            }
        }

        // ---- epi: gumbel softmax in log2 domain.
        //  a2 = 14.42695*(logit) - 10*log2(-ln u)   [== (logit+g)/tau * log2e]
        {
            const int e_lo = base + r0 + g, e_hi = e_lo + 8;
            const bool vlo = e_lo < E, vhi = e_hi < E;
            float alo[16], ahi[16];
            float mlo = -1e30f, mhi = -1e30f;
            #pragma unroll
            for (int ns = 0; ns < 8; ns++) {
                int c = ns * 8 + 2 * t;
                float b2x = sb2[c], b2y = sb2[c + 1];
                float2 ul = vlo ? *(const float2*)(u + (size_t)e_lo * 64 + c)
                               : make_float2(0.5f, 0.5f);
                float2 uh = vhi ? *(const float2*)(u + (size_t)e_hi * 64 + c)
                               : make_float2(0.5f, 0.5f);
                // w = -ln(u) + 1e-10;  contribution = -10*log2(w)
                float wl0 = fmaf(__log2f(ul.x), -0.69314718f, 1e-10f);
                float wl1 = fmaf(__log2f(ul.y), -0.69314718f, 1e-10f);
                float wh0 = fmaf(__log2f(uh.x), -0.69314718f, 1e-10f);
                float wh1 = fmaf(__log2f(uh.y), -0.69314718f, 1e-10f);
                float t00 = fmaf(acc2[ns][0], 14.42695041f, b2x);
                float t01 = fmaf(acc2[ns][1], 14.42695041f, b2y);
                float t10 = fmaf(acc2[ns][2], 14.42695041f, b2x);
                float t11 = fmaf(acc2[ns][3], 14.42695041f, b2y);
                alo[2*ns]   = fmaf(__log2f(wl0), -10.0f, t00);
                alo[2*ns+1] = fmaf(__log2f(wl1), -10.0f, t01);
                ahi[2*ns]   = fmaf(__log2f(wh0), -10.0f, t10);
                ahi[2*ns+1] = fmaf(__log2f(wh1), -10.0f, t11);
                mlo = fmaxf(mlo, fmaxf(alo[2*ns], alo[2*ns+1]));
                mhi = fmaxf(mhi, fmaxf(ahi[2*ns], ahi[2*ns+1]));
            }
            mlo = fmaxf(mlo, __shfl_xor_sync(FULL, mlo, 1));
            mlo = fmaxf(mlo, __shfl_xor_sync(FULL, mlo, 2));
            mhi = fmaxf(mhi, __shfl_xor_sync(FULL, mhi, 1));
            mhi = fmaxf(mhi, __shfl_xor_sync(FULL, mhi, 2));
            float slo = 0.f, shi = 0.f;
            #pragma unroll
            for (int i = 0; i < 16; i++) {
                float dl = alo[i] - mlo, dh = ahi[i] - mhi;
                // 2^-24 < 1e-7 final cutoff: predicate off the MUFU + sum
                alo[i] = (dl > -24.f) ? exp2f(dl) : 0.f;
                ahi[i] = (dh > -24.f) ? exp2f(dh) : 0.f;
                slo += alo[i]; shi += ahi[i];
            }
            slo += __shfl_xor_sync(FULL, slo, 1);
            slo += __shfl_xor_sync(FULL, slo, 2);
            shi += __shfl_xor_sync(FULL, shi, 1);
            shi += __shfl_xor_sync(FULL, shi, 2);
            float ilo = __fdividef(1.0f, slo), ihi = __fdividef(1.0f, shi);
            // softmax strictly positive -> int compare == float compare.
            // skip values < 1e-7: y abs error <= 1e-7, invisible at 1e-3 rel_err
            if (vlo) {
                int* yp = (int*)(g_y + (size_t)dst[e_lo] * 64);
                #pragma unroll
                for (int ns = 0; ns < 8; ns++) {
                    float v0 = alo[2*ns] * ilo, v1 = alo[2*ns+1] * ilo;
                    if (v0 > 1e-7f) atomicMax(yp + ns*8 + 2*t,     __float_as_int(v0));
                    if (v1 > 1e-7f) atomicMax(yp + ns*8 + 2*t + 1, __float_as_int(v1));
                }
            }
            if (vhi) {
                int* yp = (int*)(g_y + (size_t)dst[e_hi] * 64);
                #pragma unroll
                for (int ns = 0; ns < 8; ns++) {
                    float v0 = ahi[2*ns] * ihi, v1 = ahi[2*ns+1] * ihi;
                    if (v0 > 1e-7f) atomicMax(yp + ns*8 + 2*t,     __float_as_int(v0));
                    if (v1 > 1e-7f) atomicMax(yp + ns*8 + 2*t + 1, __float_as_int(v1));
                }
            }
        }
    }
}

// ---------------------------------------------------------------------------
// node kernel (mma.sync tf32): 8 warps/CTA, warp = 16 nodes
//   dec = relu(y[16,64] @ Wdec + b)             (ks 0..7, ns 0..15)
//   gi  = [x|dec](16,192) @ Wih^T  (3 gate passes, ns groups of 8)
//   gh  = z(16,64) @ Whh^T
//   GRU gates + output
// ---------------------------------------------------------------------------
__global__ void __launch_bounds__(256, 1)
node_kernel(const float* __restrict__ x,
            const float* __restrict__ z,
            const float* __restrict__ bdec,
            const float* __restrict__ bih,
            const float* __restrict__ bhh,
            float* __restrict__ out,
            int N, int HALF, int two)
{
    extern __shared__ float nsm[];
    const int tid = threadIdx.x, warp = tid >> 5, lane = tid & 31;
    const int t = lane & 3, g = lane >> 2;

    float* sbr   = nsm + NOD_BR;
    float* sbin  = nsm + NOD_BIN;
    float* sbhn  = nsm + NOD_BHN;
    float* sbdec = nsm + NOD_BDEC;
    if (tid < 128) sbr[tid] = bih[tid] + bhh[tid];
    if (tid < 64)  { sbin[tid] = bih[128 + tid]; sbhn[tid] = bhh[128 + tid]; }
    if (tid < 128) sbdec[tid] = bdec[tid];
    __syncthreads();

    const int nb = (blockIdx.x * 8 + warp) * 16;
    if (nb >= N) return;

    float* strip = nsm + NOD_STRIP + warp * 3136;   // 16 x 196: x | dec
    float* yb    = nsm + NOD_YB    + warp * 1088;   // 16 x 68 tf32
    float* zb    = nsm + NOD_ZB    + warp * 1088;   // 16 x 68 fp32

    // ---- load x (tf32), y (tf32), z (fp32)
    {
        int r = lane >> 1, ch = (lane & 1) * 32;
        int n = min(nb + r, N - 1);
        const float4* xp = (const float4*)(x + (size_t)n * 64 + ch);
        const float4* yp = (const float4*)(g_y + (size_t)n * 64 + ch);
        const float4* zp = (const float4*)(z + (size_t)n * 64 + ch);
        float* sx = strip + r * 196 + ch;
        float* sy = yb + r * 68 + ch;
        float* sz = zb + r * 68 + ch;
        #pragma unroll
        for (int i = 0; i < 8; i++) {
            float4 vx = xp[i], vy = yp[i], vz = zp[i];
            sx[i*4+0] = tf32f(vx.x); sx[i*4+1] = tf32f(vx.y);
            sx[i*4+2] = tf32f(vx.z); sx[i*4+3] = tf32f(vx.w);
            sy[i*4+0] = tf32f(vy.x); sy[i*4+1] = tf32f(vy.y);
            sy[i*4+2] = tf32f(vy.z); sy[i*4+3] = tf32f(vy.w);
            *(float4*)(sz + i*4) = vz;
        }
    }
    __syncwarp();

    // ---- dec GEMM: 16 accs, ks-outer
    {
        float acc[16][4];
        #pragma unroll
        for (int ns = 0; ns < 16; ns++) {
            int c = ns * 8 + 2 * t;
            acc[ns][0] = sbdec[c]; acc[ns][1] = sbdec[c + 1];
            acc[ns][2] = sbdec[c]; acc[ns][3] = sbdec[c + 1];
        }
        for (int ks = 0; ks < 8; ks++) {
            uint32_t a0 = __float_as_uint(yb[g * 68 + ks * 8 + t]);
            uint32_t a1 = __float_as_uint(yb[(g + 8) * 68 + ks * 8 + t]);
            uint32_t a2 = __float_as_uint(yb[g * 68 + ks * 8 + t + 4]);
            uint32_t a3 = __float_as_uint(yb[(g + 8) * 68 + ks * 8 + t + 4]);
            #pragma unroll
            for (int ns = 0; ns < 16; ns++) {
                float2 b = __ldg(&g_WdecF[(ns * 8 + ks) * 32 + lane]);
                mma8(acc[ns], a0, a1, a2, a3,
                     __float_as_uint(b.x), __float_as_uint(b.y));
            }
        }
        #pragma unroll
        for (int ns = 0; ns < 16; ns++) {
            int c = 64 + ns * 8 + 2 * t;
            strip[g * 196 + c]           = tf32f(fmaxf(acc[ns][0], 0.f));
            strip[g * 196 + c + 1]       = tf32f(fmaxf(acc[ns][1], 0.f));
            strip[(g + 8) * 196 + c]     = tf32f(fmaxf(acc[ns][2], 0.f));
            strip[(g + 8) * 196 + c + 1] = tf32f(fmaxf(acc[ns][3], 0.f));
        }
    }
    __syncwarp();

    // ---- gate passes
    float rg[8][4], zg[8][4], ai[8][4], ah[8][4];

    #pragma unroll
    for (int p = 0; p < 2; p++) {               // p=0: r gate, p=1: z gate
        const int ns0 = p * 8;
        float acc[8][4];
        #pragma unroll
        for (int ns = 0; ns < 8; ns++) {
            int c = (ns0 + ns) * 8 + 2 * t;
            acc[ns][0] = sbr[c]; acc[ns][1] = sbr[c + 1];
            acc[ns][2] = sbr[c]; acc[ns][3] = sbr[c + 1];
        }
        for (int ks = 0; ks < 24; ks++) {       // gi: A = strip(x|dec)
            uint32_t a0 = __float_as_uint(strip[g * 196 + ks * 8 + t]);
            uint32_t a1 = __float_as_uint(strip[(g + 8) * 196 + ks * 8 + t]);
            uint32_t a2 = __float_as_uint(strip[g * 196 + ks * 8 + t + 4]);
            uint32_t a3 = __float_as_uint(strip[(g + 8) * 196 + ks * 8 + t + 4]);
            #pragma unroll
            for (int ns = 0; ns < 8; ns++) {
                float2 b = __ldg(&g_WihF[((ns0 + ns) * 24 + ks) * 32 + lane]);
                mma8(acc[ns], a0, a1, a2, a3,
                     __float_as_uint(b.x), __float_as_uint(b.y));
            }
        }
        for (int ks = 0; ks < 8; ks++) {        // gh: A = z (cvt tf32)
            uint32_t a0 = cvt_tf32(zb[g * 68 + ks * 8 + t]);
            uint32_t a1 = cvt_tf32(zb[(g + 8) * 68 + ks * 8 + t]);
            uint32_t a2 = cvt_tf32(zb[g * 68 + ks * 8 + t + 4]);
            uint32_t a3 = cvt_tf32(zb[(g + 8) * 68 + ks * 8 + t + 4]);
            #pragma unroll
            for (int ns = 0; ns < 8; ns++) {
                float2 b = __ldg(&g_WhhF[((ns0 + ns) * 8 + ks) * 32 + lane]);
                mma8(acc[ns], a0, a1, a2, a3,
                     __float_as_uint(b.x), __float_as_uint(b.y));
            }
        }
        #pragma unroll
        for (int ns = 0; ns < 8; ns++)
            #pragma unroll
            for (int q = 0; q < 4; q++) {
                float s = sigmoidf(acc[ns][q]);
                if (p == 0) rg[ns][q] = s; else zg[ns][q] = s;
            }
    }

    // n gate: i_n and h_n separate
    #pragma unroll
    for (int ns = 0; ns < 8; ns++) {
        int c = ns * 8 + 2 * t;
        ai[ns][0] = sbin[c]; ai[ns][1] = sbin[c + 1];
        ai[ns][2] = sbin[c]; ai[ns][3] = sbin[c + 1];
        ah[ns][0] = sbhn[c]; ah[ns][1] = sbhn[c + 1];
        ah[ns][2] = sbhn[c]; ah[ns][3] = sbhn[c + 1];
    }
    for (int ks = 0; ks < 24; ks++) {
        uint32_t a0 = __float_as_uint(strip[g * 196 + ks * 8 + t]);
        uint32_t a1 = __float_as_uint(strip[(g + 8) * 196 + ks * 8 + t]);
        uint32_t a2 = __float_as_uint(strip[g * 196 + ks * 8 + t + 4]);
        uint32_t a3 = __float_as_uint(strip[(g + 8) * 196 + ks * 8 + t + 4]);
        #pragma unroll
        for (int ns = 0; ns < 8; ns++) {
            float2 b = __ldg(&g_WihF[((16 + ns) * 24 + ks) * 32 + lane]);
            mma8(ai[ns], a0, a1, a2, a3,
                 __float_as_uint(b.x), __float_as_uint(b.y));
        }
    }
    for (int ks = 0; ks < 8; ks++) {
        uint32_t a0 = cvt_tf32(zb[g * 68 + ks * 8 + t]);
        uint32_t a1 = cvt_tf32(zb[(g + 8) * 68 + ks * 8 + t]);
        uint32_t a2 = cvt_tf32(zb[g * 68 + ks * 8 + t + 4]);
        uint32_t a3 = cvt_tf32(zb[(g + 8) * 68 + ks * 8 + t + 4]);
        #pragma unroll
        for (int ns = 0; ns < 8; ns++) {
            float2 b = __ldg(&g_WhhF[((16 + ns) * 8 + ks) * 32 + lane]);
            mma8(ah[ns], a0, a1, a2, a3,
                 __float_as_uint(b.x), __float_as_uint(b.y));
        }
    }

    // ---- combine gates + write (rows nb+g, nb+g+8; cols ns*8+2t, +1)
    const int R0 = nb + g, R1 = nb + g + 8;
    #pragma unroll
    for (int ns = 0; ns < 8; ns++) {
        int o = ns * 8 + 2 * t;
        float n00 = tanhf(ai[ns][0] + rg[ns][0] * ah[ns][0]);
        float n01 = tanhf(ai[ns][1] + rg[ns][1] * ah[ns][1]);
        float n10 = tanhf(ai[ns][2] + rg[ns][2] * ah[ns][2]);
        float n11 = tanhf(ai[ns][3] + rg[ns][3] * ah[ns][3]);
        float z00 = zb[g * 68 + o],       z01 = zb[g * 68 + o + 1];
        float z10 = zb[(g + 8) * 68 + o], z11 = zb[(g + 8) * 68 + o + 1];
        float h00 = (1.f - zg[ns][0]) * n00 + zg[ns][0] * z00;
        float h01 = (1.f - zg[ns][1]) * n01 + zg[ns][1] * z01;
        float h10 = (1.f - zg[ns][2]) * n10 + zg[ns][2] * z10;
        float h11 = (1.f - zg[ns][3]) * n11 + zg[ns][3] * z11;
        if (R0 < N) {
            *(float2*)(out + (size_t)R0 * 64 + o) = make_float2(h00, h01);
            if (two) *(float2*)(out + HALF + (size_t)R0 * 64 + o) = make_float2(h00, h01);
        }
        if (R1 < N) {
            *(float2*)(out + (size_t)R1 * 64 + o) = make_float2(h10, h11);
            if (two) *(float2*)(out + HALF + (size_t)R1 * 64 + o) = make_float2(h10, h11);
        }
    }
}

// ---------------------------------------------------------------------------
// launch
// inputs: x, z, src, dst, u, W_enc1, b_enc1, W_enc2, b_enc2,
//         W_dec, b_dec, W_ih, b_ih, W_hh, b_hh
// ---------------------------------------------------------------------------
extern "C" void kernel_launch(void* const* d_in, const int* in_sizes, int n_in,
                              void* d_out, int out_size)
{
    const float* x     = (const float*)d_in[0];
    const float* z     = (const float*)d_in[1];
    const int*   src   = (const int*)  d_in[2];
    const int*   dst   = (const int*)  d_in[3];
    const float* u     = (const float*)d_in[4];
    const float* W1    = (const float*)d_in[5];
    const float* b1    = (const float*)d_in[6];
    const float* W2    = (const float*)d_in[7];
    const float* b2    = (const float*)d_in[8];
    const float* Wdec  = (const float*)d_in[9];
    const float* bdec  = (const float*)d_in[10];
    const float* Wih   = (const float*)d_in[11];
    const float* bih   = (const float*)d_in[12];
    const float* Whh   = (const float*)d_in[13];
    const float* bhh   = (const float*)d_in[14];

    const int N = in_sizes[0] / FDIM;
    const int E = in_sizes[2];
    float* out = (float*)d_out;
    const int HALF = N * OUTF;
    const int two = (out_size >= 2 * HALF) ? 1 : 0;

    // init mailbox + fragment packs
    {
        int total = N * MSG;
        init_kernel<<<(total + 255) / 256, 256>>>(Wih, Whh, Wdec, N);
    }

    // edge kernel: persistent mma.sync tf32
    {
        cudaFuncSetAttribute(edge_mma_kernel,
                             cudaFuncAttributeMaxDynamicSharedMemorySize, SMEM_EDGE);
        edge_mma_kernel<<<148, 512, SMEM_EDGE>>>(x, src, dst, u, W1, b1, W2, b2, E);
    }

    // node kernel: mma.sync tf32
    {
        cudaFuncSetAttribute(node_kernel,
                             cudaFuncAttributeMaxDynamicSharedMemorySize, SMEM_NODE);
        int blocks = (N + 127) / 128;
        node_kernel<<<blocks, 256, SMEM_NODE>>>(x, z, bdec, bih, bhh, out, N, HALF, two);
    }
}

// round 8
// speedup vs baseline: 3.4500x; 1.1218x over previous
#include <cuda_runtime.h>
#include <math.h>
#include <stdint.h>

#define FDIM 64
#define HIDD 128
#define MSG  64
#define OUTF 64
#define NMAX 50000

// scratch (no cudaMalloc allowed)
__device__ float g_y[NMAX * MSG];            // mailbox max, 12.8 MB
__device__ float2 g_WdecF[16 * 8 * 32];      // mma B-frags for Wdec
__device__ float2 g_WihF[24 * 24 * 32];      // mma B-frags for W_ih (gi)
__device__ float2 g_WhhF[24 * 8 * 32];       // mma B-frags for W_hh (gh)

// ===========================================================================
// helpers
// ===========================================================================
__device__ __forceinline__ uint32_t cvt_tf32(float f) {
    uint32_t r; asm("cvt.rna.tf32.f32 %0, %1;" : "=r"(r) : "f"(f)); return r;
}
__device__ __forceinline__ float tf32f(float f) {
    return __uint_as_float(cvt_tf32(f));
}
// D += A(16x8) * B(8x8), tf32 inputs, f32 accum  (arch-portable: sm_80+)
__device__ __forceinline__ void mma8(float* c, uint32_t a0, uint32_t a1,
                                     uint32_t a2, uint32_t a3,
                                     uint32_t b0, uint32_t b1) {
    asm volatile(
        "mma.sync.aligned.m16n8k8.row.col.f32.tf32.tf32.f32 "
        "{%0,%1,%2,%3}, {%4,%5,%6,%7}, {%8,%9}, {%0,%1,%2,%3};"
        : "+f"(c[0]), "+f"(c[1]), "+f"(c[2]), "+f"(c[3])
        : "r"(a0), "r"(a1), "r"(a2), "r"(a3), "r"(b0), "r"(b1));
}
__device__ __forceinline__ float sigmoidf(float v) {
    return __fdividef(1.0f, 1.0f + __expf(-v));
}

// edge kernel smem layout (bytes)
#define OFF_W1F   0                    // 16 ns x 8 ks x 32 lane x float2 = 32KB
#define OFF_W2F   32768                // 8 ns x 16 ks x 32 lane x float2 = 32KB
#define OFF_SB1   65536                // 128 f
#define OFF_SB2   66048                // 64 f  (pre-scaled 14.42695*b2)
#define OFF_STRIP 66304                // 16 warps x 2112 floats (16 rows x 132, H only)
#define STRIP_F   2112
#define SMEM_EDGE (OFF_STRIP + 16 * STRIP_F * 4)   // 201472

// node kernel smem layout (floats)
#define NOD_STRIP 0                    // 8 warps x 16 x 196
#define NOD_YB    (8 * 3136)           // 8 warps x 16 x 68
#define NOD_ZB    (NOD_YB + 8 * 1088)
#define NOD_BR    (NOD_ZB + 8 * 1088)  // 128: bih+bhh (r,z gates)
#define NOD_BIN   (NOD_BR + 128)       // 64: bih n-gate
#define NOD_BHN   (NOD_BIN + 64)       // 64: bhh n-gate
#define NOD_BDEC  (NOD_BHN + 64)       // 128
#define SMEM_NODE ((NOD_BDEC + 128) * 4)

// ---------------------------------------------------------------------------
// init: zero mailbox + pack node-GEMM weight fragments
// ---------------------------------------------------------------------------
__global__ void init_kernel(const float* __restrict__ W_ih,
                            const float* __restrict__ W_hh,
                            const float* __restrict__ Wdec, int N)
{
    int idx = blockIdx.x * blockDim.x + threadIdx.x;
    if (idx < N * MSG) g_y[idx] = 0.0f;
    int lane = idx & 31, g = lane >> 2, t = lane & 3;
    if (idx < 16 * 8 * 32) {                 // WdecF: B[k=j][n=h] = Wdec[j*128+h]
        int ks = (idx >> 5) & 7, ns = idx >> 8;
        g_WdecF[idx] = make_float2(
            tf32f(Wdec[(ks * 8 + t) * 128 + ns * 8 + g]),
            tf32f(Wdec[(ks * 8 + t + 4) * 128 + ns * 8 + g]));
    }
    if (idx < 24 * 24 * 32) {                // WihF: B[k=i][n=o] = W_ih[o*192+i]
        int ks = (idx >> 5) % 24, ns = (idx >> 5) / 24;
        g_WihF[idx] = make_float2(
            tf32f(W_ih[(ns * 8 + g) * 192 + ks * 8 + t]),
            tf32f(W_ih[(ns * 8 + g) * 192 + ks * 8 + t + 4]));
    }
    if (idx < 24 * 8 * 32) {                 // WhhF: B[k=j][n=o] = W_hh[o*64+j]
        int ks = (idx >> 5) & 7, ns = idx >> 8;
        g_WhhF[idx] = make_float2(
            tf32f(W_hh[(ns * 8 + g) * 64 + ks * 8 + t]),
            tf32f(W_hh[(ns * 8 + g) * 64 + ks * 8 + t + 4]));
    }
}

// ---------------------------------------------------------------------------
// edge kernel (mma.sync tf32): persistent, tile = 256 edges, warp = 16 edges
//   gather: x[src] straight into GEMM1 A-fragment registers (no smem round-trip)
//   GEMM1: H[16,128] = X[16,64] @ W1, relu+bias -> strip (smem)
//   GEMM2: L[16,64]  = H[16,128] @ W2
//   epi:   gumbel softmax in log2 domain + thresholded atomicMax scatter
// ---------------------------------------------------------------------------
__global__ void __launch_bounds__(512, 1)
edge_mma_kernel(const float* __restrict__ x, const int* __restrict__ src,
                const int* __restrict__ dst, const float* __restrict__ u,
                const float* __restrict__ W1, const float* __restrict__ b1,
                const float* __restrict__ W2, const float* __restrict__ b2,
                int E)
{
    extern __shared__ unsigned char smraw[];
    float2* w1f = (float2*)(smraw + OFF_W1F);
    float2* w2f = (float2*)(smraw + OFF_W2F);
    float*  sb1 = (float*)(smraw + OFF_SB1);
    float*  sb2 = (float*)(smraw + OFF_SB2);

    const int tid = threadIdx.x;
    const int warp = tid >> 5, lane = tid & 31;
    const int t = lane & 3, g = lane >> 2;
    const unsigned FULL = 0xffffffffu;
    float* strip = (float*)(smraw + OFF_STRIP) + warp * STRIP_F;

    // ---- pack weights into mma fragment order (tf32-rounded), once
    for (int idx = tid; idx < 16 * 8 * 32; idx += 512) {
        int ln = idx & 31, ks = (idx >> 5) & 7, ns = idx >> 8;
        int tt = ln & 3, gg = ln >> 2;
        w1f[idx] = make_float2(tf32f(W1[(ks * 8 + tt) * 128 + ns * 8 + gg]),
                               tf32f(W1[(ks * 8 + tt + 4) * 128 + ns * 8 + gg]));
    }
    for (int idx = tid; idx < 8 * 16 * 32; idx += 512) {
        int ln = idx & 31, ks = (idx >> 5) & 15, ns = idx >> 9;
        int tt = ln & 3, gg = ln >> 2;
        w2f[idx] = make_float2(tf32f(W2[(ks * 8 + tt) * 64 + ns * 8 + gg]),
                               tf32f(W2[(ks * 8 + tt + 4) * 64 + ns * 8 + gg]));
    }
    if (tid < 128) sb1[tid] = b1[tid];
    if (tid < 64)  sb2[tid] = 14.42695041f * b2[tid];   // 10/tau * log2(e) folded
    __syncthreads();

    const int ntiles = (E + 255) >> 8;
    const int r0 = warp * 16;

    for (int tile = blockIdx.x; tile < ntiles; tile += gridDim.x) {
        const int base = tile << 8;
        __syncwarp();   // strip reuse across tiles (prev GEMM2 reads done)

        // ---- prefetch this warp's u rows to L2 (16 rows x 256B = 32 lines)
        {
            int row = lane >> 1;
            int half = (lane & 1) * 32;
            const float* up = u + (size_t)min(base + r0 + row, E - 1) * 64 + half;
            asm volatile("prefetch.global.L2 [%0];" :: "l"(up));
        }

        // ---- gather x[src] directly into A-fragment registers (tf32)
        const int e_lo = base + r0 + g, e_hi = e_lo + 8;
        float ax0[8], ax1[8], ax2[8], ax3[8];
        {
            int s_lo = src[min(e_lo, E - 1)];
            int s_hi = src[min(e_hi, E - 1)];
            const float* xlo = x + (size_t)s_lo * 64;
            const float* xhi = x + (size_t)s_hi * 64;
            #pragma unroll
            for (int ks = 0; ks < 8; ks++) {
                ax0[ks] = tf32f(xlo[ks * 8 + t]);
                ax1[ks] = tf32f(xhi[ks * 8 + t]);
                ax2[ks] = tf32f(xlo[ks * 8 + t + 4]);
                ax3[ks] = tf32f(xhi[ks * 8 + t + 4]);
            }
        }

        // ---- GEMM1 in two passes of 8 n-slabs (A in registers)
        #pragma unroll
        for (int pass = 0; pass < 2; pass++) {
            const int nbase = pass * 8;
            float acc[8][4];
            #pragma unroll
            for (int ns = 0; ns < 8; ns++)
                { acc[ns][0] = acc[ns][1] = acc[ns][2] = acc[ns][3] = 0.f; }

            #pragma unroll
            for (int ks = 0; ks < 8; ks++) {
                uint32_t a0 = __float_as_uint(ax0[ks]);
                uint32_t a1 = __float_as_uint(ax1[ks]);
                uint32_t a2 = __float_as_uint(ax2[ks]);
                uint32_t a3 = __float_as_uint(ax3[ks]);
                #pragma unroll
                for (int ns = 0; ns < 8; ns++) {
                    float2 b = w1f[((nbase + ns) * 8 + ks) * 32 + lane];
                    mma8(acc[ns], a0, a1, a2, a3,
                         __float_as_uint(b.x), __float_as_uint(b.y));
                }
            }
            #pragma unroll
            for (int ns = 0; ns < 8; ns++) {
                int c = (nbase + ns) * 8 + 2 * t;
                float bx = sb1[c], by = sb1[c + 1];
                *(float2*)(strip + g * 132 + c) =
                    make_float2(tf32f(fmaxf(acc[ns][0] + bx, 0.f)),
                                tf32f(fmaxf(acc[ns][1] + by, 0.f)));
                *(float2*)(strip + (g + 8) * 132 + c) =
                    make_float2(tf32f(fmaxf(acc[ns][2] + bx, 0.f)),
                                tf32f(fmaxf(acc[ns][3] + by, 0.f)));
            }
        }
        __syncwarp();   // H visible to whole warp before GEMM2

        // ---- GEMM2: L[16,64] = H[16,128] @ W2
        float acc2[8][4];
        #pragma unroll
        for (int ns = 0; ns < 8; ns++)
            { acc2[ns][0] = acc2[ns][1] = acc2[ns][2] = acc2[ns][3] = 0.f; }
        for (int ks = 0; ks < 16; ks++) {
            uint32_t a0 = __float_as_uint(strip[g * 132 + ks * 8 + t]);
            uint32_t a1 = __float_as_uint(strip[(g + 8) * 132 + ks * 8 + t]);
            uint32_t a2 = __float_as_uint(strip[g * 132 + ks * 8 + t + 4]);
            uint32_t a3 = __float_as_uint(strip[(g + 8) * 132 + ks * 8 + t + 4]);
            #pragma unroll
            for (int ns = 0; ns < 8; ns++) {
                float2 b = w2f[(ns * 16 + ks) * 32 + lane];
                mma8(acc2[ns], a0, a1, a2, a3,
                     __float_as_uint(b.x), __float_as_uint(b.y));
            }
        }

        // ---- epi: gumbel softmax in log2 domain.
        //  a = 14.42695*(logit) - 10*log2(-ln u)   [== (logit+g)/tau * log2e]
        {
            const bool vlo = e_lo < E, vhi = e_hi < E;
            float alo[16], ahi[16];
            float mlo = -1e30f, mhi = -1e30f;
            #pragma unroll
            for (int ns = 0; ns < 8; ns++) {
                int c = ns * 8 + 2 * t;
                float b2x = sb2[c], b2y = sb2[c + 1];
                float2 ul = vlo ? *(const float2*)(u + (size_t)e_lo * 64 + c)
                               : make_float2(0.5f, 0.5f);
                float2 uh = vhi ? *(const float2*)(u + (size_t)e_hi * 64 + c)
                               : make_float2(0.5f, 0.5f);
                // w = -ln(u) + 1e-10;  contribution = -10*log2(w)
                float wl0 = fmaf(__log2f(ul.x), -0.69314718f, 1e-10f);
                float wl1 = fmaf(__log2f(ul.y), -0.69314718f, 1e-10f);
                float wh0 = fmaf(__log2f(uh.x), -0.69314718f, 1e-10f);
                float wh1 = fmaf(__log2f(uh.y), -0.69314718f, 1e-10f);
                float t00 = fmaf(acc2[ns][0], 14.42695041f, b2x);
                float t01 = fmaf(acc2[ns][1], 14.42695041f, b2y);
                float t10 = fmaf(acc2[ns][2], 14.42695041f, b2x);
                float t11 = fmaf(acc2[ns][3], 14.42695041f, b2y);
                alo[2*ns]   = fmaf(__log2f(wl0), -10.0f, t00);
                alo[2*ns+1] = fmaf(__log2f(wl1), -10.0f, t01);
                ahi[2*ns]   = fmaf(__log2f(wh0), -10.0f, t10);
                ahi[2*ns+1] = fmaf(__log2f(wh1), -10.0f, t11);
                mlo = fmaxf(mlo, fmaxf(alo[2*ns], alo[2*ns+1]));
                mhi = fmaxf(mhi, fmaxf(ahi[2*ns], ahi[2*ns+1]));
            }
            mlo = fmaxf(mlo, __shfl_xor_sync(FULL, mlo, 1));
            mlo = fmaxf(mlo, __shfl_xor_sync(FULL, mlo, 2));
            mhi = fmaxf(mhi, __shfl_xor_sync(FULL, mhi, 1));
            mhi = fmaxf(mhi, __shfl_xor_sync(FULL, mhi, 2));
            float slo = 0.f, shi = 0.f;
            #pragma unroll
            for (int i = 0; i < 16; i++) {
                float dl = alo[i] - mlo, dh = ahi[i] - mhi;
                // 2^-24 < 1e-7 final cutoff: predicate off the MUFU + sum
                alo[i] = (dl > -24.f) ? exp2f(dl) : 0.f;
                ahi[i] = (dh > -24.f) ? exp2f(dh) : 0.f;
                slo += alo[i]; shi += ahi[i];
            }
            slo += __shfl_xor_sync(FULL, slo, 1);
            slo += __shfl_xor_sync(FULL, slo, 2);
            shi += __shfl_xor_sync(FULL, shi, 1);
            shi += __shfl_xor_sync(FULL, shi, 2);
            float ilo = __fdividef(1.0f, slo), ihi = __fdividef(1.0f, shi);
            // softmax strictly positive -> int compare == float compare.
            // skip values < 1e-7: y abs error <= 1e-7, invisible at 1e-3 rel_err
            if (vlo) {
                int* yp = (int*)(g_y + (size_t)dst[e_lo] * 64);
                #pragma unroll
                for (int ns = 0; ns < 8; ns++) {
                    float v0 = alo[2*ns] * ilo, v1 = alo[2*ns+1] * ilo;
                    if (v0 > 1e-7f) atomicMax(yp + ns*8 + 2*t,     __float_as_int(v0));
                    if (v1 > 1e-7f) atomicMax(yp + ns*8 + 2*t + 1, __float_as_int(v1));
                }
            }
            if (vhi) {
                int* yp = (int*)(g_y + (size_t)dst[e_hi] * 64);
                #pragma unroll
                for (int ns = 0; ns < 8; ns++) {
                    float v0 = ahi[2*ns] * ihi, v1 = ahi[2*ns+1] * ihi;
                    if (v0 > 1e-7f) atomicMax(yp + ns*8 + 2*t,     __float_as_int(v0));
                    if (v1 > 1e-7f) atomicMax(yp + ns*8 + 2*t + 1, __float_as_int(v1));
                }
            }
        }
    }
}

// ---------------------------------------------------------------------------
// node kernel (mma.sync tf32): 8 warps/CTA, warp = 16 nodes  (unchanged)
// ---------------------------------------------------------------------------
__global__ void __launch_bounds__(256, 1)
node_kernel(const float* __restrict__ x,
            const float* __restrict__ z,
            const float* __restrict__ bdec,
            const float* __restrict__ bih,
            const float* __restrict__ bhh,
            float* __restrict__ out,
            int N, int HALF, int two)
{
    extern __shared__ float nsm[];
    const int tid = threadIdx.x, warp = tid >> 5, lane = tid & 31;
    const int t = lane & 3, g = lane >> 2;

    float* sbr   = nsm + NOD_BR;
    float* sbin  = nsm + NOD_BIN;
    float* sbhn  = nsm + NOD_BHN;
    float* sbdec = nsm + NOD_BDEC;
    if (tid < 128) sbr[tid] = bih[tid] + bhh[tid];
    if (tid < 64)  { sbin[tid] = bih[128 + tid]; sbhn[tid] = bhh[128 + tid]; }
    if (tid < 128) sbdec[tid] = bdec[tid];
    __syncthreads();

    const int nb = (blockIdx.x * 8 + warp) * 16;
    if (nb >= N) return;

    float* strip = nsm + NOD_STRIP + warp * 3136;   // 16 x 196: x | dec
    float* yb    = nsm + NOD_YB    + warp * 1088;   // 16 x 68 tf32
    float* zb    = nsm + NOD_ZB    + warp * 1088;   // 16 x 68 fp32

    // ---- load x (tf32), y (tf32), z (fp32)
    {
        int r = lane >> 1, ch = (lane & 1) * 32;
        int n = min(nb + r, N - 1);
        const float4* xp = (const float4*)(x + (size_t)n * 64 + ch);
        const float4* yp = (const float4*)(g_y + (size_t)n * 64 + ch);
        const float4* zp = (const float4*)(z + (size_t)n * 64 + ch);
        float* sx = strip + r * 196 + ch;
        float* sy = yb + r * 68 + ch;
        float* sz = zb + r * 68 + ch;
        #pragma unroll
        for (int i = 0; i < 8; i++) {
            float4 vx = xp[i], vy = yp[i], vz = zp[i];
            sx[i*4+0] = tf32f(vx.x); sx[i*4+1] = tf32f(vx.y);
            sx[i*4+2] = tf32f(vx.z); sx[i*4+3] = tf32f(vx.w);
            sy[i*4+0] = tf32f(vy.x); sy[i*4+1] = tf32f(vy.y);
            sy[i*4+2] = tf32f(vy.z); sy[i*4+3] = tf32f(vy.w);
            *(float4*)(sz + i*4) = vz;
        }
    }
    __syncwarp();

    // ---- dec GEMM: 16 accs, ks-outer
    {
        float acc[16][4];
        #pragma unroll
        for (int ns = 0; ns < 16; ns++) {
            int c = ns * 8 + 2 * t;
            acc[ns][0] = sbdec[c]; acc[ns][1] = sbdec[c + 1];
            acc[ns][2] = sbdec[c]; acc[ns][3] = sbdec[c + 1];
        }
        for (int ks = 0; ks < 8; ks++) {
            uint32_t a0 = __float_as_uint(yb[g * 68 + ks * 8 + t]);
            uint32_t a1 = __float_as_uint(yb[(g + 8) * 68 + ks * 8 + t]);
            uint32_t a2 = __float_as_uint(yb[g * 68 + ks * 8 + t + 4]);
            uint32_t a3 = __float_as_uint(yb[(g + 8) * 68 + ks * 8 + t + 4]);
            #pragma unroll
            for (int ns = 0; ns < 16; ns++) {
                float2 b = __ldg(&g_WdecF[(ns * 8 + ks) * 32 + lane]);
                mma8(acc[ns], a0, a1, a2, a3,
                     __float_as_uint(b.x), __float_as_uint(b.y));
            }
        }
        #pragma unroll
        for (int ns = 0; ns < 16; ns++) {
            int c = 64 + ns * 8 + 2 * t;
            strip[g * 196 + c]           = tf32f(fmaxf(acc[ns][0], 0.f));
            strip[g * 196 + c + 1]       = tf32f(fmaxf(acc[ns][1], 0.f));
            strip[(g + 8) * 196 + c]     = tf32f(fmaxf(acc[ns][2], 0.f));
            strip[(g + 8) * 196 + c + 1] = tf32f(fmaxf(acc[ns][3], 0.f));
        }
    }
    __syncwarp();

    // ---- gate passes
    float rg[8][4], zg[8][4], ai[8][4], ah[8][4];

    #pragma unroll
    for (int p = 0; p < 2; p++) {               // p=0: r gate, p=1: z gate
        const int ns0 = p * 8;
        float acc[8][4];
        #pragma unroll
        for (int ns = 0; ns < 8; ns++) {
            int c = (ns0 + ns) * 8 + 2 * t;
            acc[ns][0] = sbr[c]; acc[ns][1] = sbr[c + 1];
            acc[ns][2] = sbr[c]; acc[ns][3] = sbr[c + 1];
        }
        for (int ks = 0; ks < 24; ks++) {       // gi: A = strip(x|dec)
            uint32_t a0 = __float_as_uint(strip[g * 196 + ks * 8 + t]);
            uint32_t a1 = __float_as_uint(strip[(g + 8) * 196 + ks * 8 + t]);
            uint32_t a2 = __float_as_uint(strip[g * 196 + ks * 8 + t + 4]);
            uint32_t a3 = __float_as_uint(strip[(g + 8) * 196 + ks * 8 + t + 4]);
            #pragma unroll
            for (int ns = 0; ns < 8; ns++) {
                float2 b = __ldg(&g_WihF[((ns0 + ns) * 24 + ks) * 32 + lane]);
                mma8(acc[ns], a0, a1, a2, a3,
                     __float_as_uint(b.x), __float_as_uint(b.y));
            }
        }
        for (int ks = 0; ks < 8; ks++) {        // gh: A = z (cvt tf32)
            uint32_t a0 = cvt_tf32(zb[g * 68 + ks * 8 + t]);
            uint32_t a1 = cvt_tf32(zb[(g + 8) * 68 + ks * 8 + t]);
            uint32_t a2 = cvt_tf32(zb[g * 68 + ks * 8 + t + 4]);
            uint32_t a3 = cvt_tf32(zb[(g + 8) * 68 + ks * 8 + t + 4]);
            #pragma unroll
            for (int ns = 0; ns < 8; ns++) {
                float2 b = __ldg(&g_WhhF[((ns0 + ns) * 8 + ks) * 32 + lane]);
                mma8(acc[ns], a0, a1, a2, a3,
                     __float_as_uint(b.x), __float_as_uint(b.y));
            }
        }
        #pragma unroll
        for (int ns = 0; ns < 8; ns++)
            #pragma unroll
            for (int q = 0; q < 4; q++) {
                float s = sigmoidf(acc[ns][q]);
                if (p == 0) rg[ns][q] = s; else zg[ns][q] = s;
            }
    }

    // n gate: i_n and h_n separate
    #pragma unroll
    for (int ns = 0; ns < 8; ns++) {
        int c = ns * 8 + 2 * t;
        ai[ns][0] = sbin[c]; ai[ns][1] = sbin[c + 1];
        ai[ns][2] = sbin[c]; ai[ns][3] = sbin[c + 1];
        ah[ns][0] = sbhn[c]; ah[ns][1] = sbhn[c + 1];
        ah[ns][2] = sbhn[c]; ah[ns][3] = sbhn[c + 1];
    }
    for (int ks = 0; ks < 24; ks++) {
        uint32_t a0 = __float_as_uint(strip[g * 196 + ks * 8 + t]);
        uint32_t a1 = __float_as_uint(strip[(g + 8) * 196 + ks * 8 + t]);
        uint32_t a2 = __float_as_uint(strip[g * 196 + ks * 8 + t + 4]);
        uint32_t a3 = __float_as_uint(strip[(g + 8) * 196 + ks * 8 + t + 4]);
        #pragma unroll
        for (int ns = 0; ns < 8; ns++) {
            float2 b = __ldg(&g_WihF[((16 + ns) * 24 + ks) * 32 + lane]);
            mma8(ai[ns], a0, a1, a2, a3,
                 __float_as_uint(b.x), __float_as_uint(b.y));
        }
    }
    for (int ks = 0; ks < 8; ks++) {
        uint32_t a0 = cvt_tf32(zb[g * 68 + ks * 8 + t]);
        uint32_t a1 = cvt_tf32(zb[(g + 8) * 68 + ks * 8 + t]);
        uint32_t a2 = cvt_tf32(zb[g * 68 + ks * 8 + t + 4]);
        uint32_t a3 = cvt_tf32(zb[(g + 8) * 68 + ks * 8 + t + 4]);
        #pragma unroll
        for (int ns = 0; ns < 8; ns++) {
            float2 b = __ldg(&g_WhhF[((16 + ns) * 8 + ks) * 32 + lane]);
            mma8(ah[ns], a0, a1, a2, a3,
                 __float_as_uint(b.x), __float_as_uint(b.y));
        }
    }

    // ---- combine gates + write (rows nb+g, nb+g+8; cols ns*8+2t, +1)
    const int R0 = nb + g, R1 = nb + g + 8;
    #pragma unroll
    for (int ns = 0; ns < 8; ns++) {
        int o = ns * 8 + 2 * t;
        float n00 = tanhf(ai[ns][0] + rg[ns][0] * ah[ns][0]);
        float n01 = tanhf(ai[ns][1] + rg[ns][1] * ah[ns][1]);
        float n10 = tanhf(ai[ns][2] + rg[ns][2] * ah[ns][2]);
        float n11 = tanhf(ai[ns][3] + rg[ns][3] * ah[ns][3]);
        float z00 = zb[g * 68 + o],       z01 = zb[g * 68 + o + 1];
        float z10 = zb[(g + 8) * 68 + o], z11 = zb[(g + 8) * 68 + o + 1];
        float h00 = (1.f - zg[ns][0]) * n00 + zg[ns][0] * z00;
        float h01 = (1.f - zg[ns][1]) * n01 + zg[ns][1] * z01;
        float h10 = (1.f - zg[ns][2]) * n10 + zg[ns][2] * z10;
        float h11 = (1.f - zg[ns][3]) * n11 + zg[ns][3] * z11;
        if (R0 < N) {
            *(float2*)(out + (size_t)R0 * 64 + o) = make_float2(h00, h01);
            if (two) *(float2*)(out + HALF + (size_t)R0 * 64 + o) = make_float2(h00, h01);
        }
        if (R1 < N) {
            *(float2*)(out + (size_t)R1 * 64 + o) = make_float2(h10, h11);
            if (two) *(float2*)(out + HALF + (size_t)R1 * 64 + o) = make_float2(h10, h11);
        }
    }
}

// ---------------------------------------------------------------------------
// launch
// inputs: x, z, src, dst, u, W_enc1, b_enc1, W_enc2, b_enc2,
//         W_dec, b_dec, W_ih, b_ih, W_hh, b_hh
// ---------------------------------------------------------------------------
extern "C" void kernel_launch(void* const* d_in, const int* in_sizes, int n_in,
                              void* d_out, int out_size)
{
    const float* x     = (const float*)d_in[0];
    const float* z     = (const float*)d_in[1];
    const int*   src   = (const int*)  d_in[2];
    const int*   dst   = (const int*)  d_in[3];
    const float* u     = (const float*)d_in[4];
    const float* W1    = (const float*)d_in[5];
    const float* b1    = (const float*)d_in[6];
    const float* W2    = (const float*)d_in[7];
    const float* b2    = (const float*)d_in[8];
    const float* Wdec  = (const float*)d_in[9];
    const float* bdec  = (const float*)d_in[10];
    const float* Wih   = (const float*)d_in[11];
    const float* bih   = (const float*)d_in[12];
    const float* Whh   = (const float*)d_in[13];
    const float* bhh   = (const float*)d_in[14];

    const int N = in_sizes[0] / FDIM;
    const int E = in_sizes[2];
    float* out = (float*)d_out;
    const int HALF = N * OUTF;
    const int two = (out_size >= 2 * HALF) ? 1 : 0;

    // init mailbox + fragment packs
    {
        int total = N * MSG;
        init_kernel<<<(total + 255) / 256, 256>>>(Wih, Whh, Wdec, N);
    }

    // edge kernel: persistent mma.sync tf32
    {
        cudaFuncSetAttribute(edge_mma_kernel,
                             cudaFuncAttributeMaxDynamicSharedMemorySize, SMEM_EDGE);
        edge_mma_kernel<<<148, 512, SMEM_EDGE>>>(x, src, dst, u, W1, b1, W2, b2, E);
    }

    // node kernel: mma.sync tf32
    {
        cudaFuncSetAttribute(node_kernel,
                             cudaFuncAttributeMaxDynamicSharedMemorySize, SMEM_NODE);
        int blocks = (N + 127) / 128;
        node_kernel<<<blocks, 256, SMEM_NODE>>>(x, z, bdec, bih, bhh, out, N, HALF, two);
    }
}